// round 16
// baseline (speedup 1.0000x reference)
#include <cuda_runtime.h>
#include <cuda_bf16.h>
#include <math.h>
#include <stdint.h>

#define SEQ    256
#define BATCH  64
#define EMBED  512
#define HIDDEN 512
#define VOCAB  10000
#define NPAD   10240
#define ROWS   (SEQ*BATCH)      /* 16384 */
#define G4     (4*HIDDEN)       /* 2048  */
#define NCTA   128
#define NTHR   256
#define NTHR_L 512
#define HSLOT  (HIDDEN*BATCH)   /* 32768 floats per h slot */

typedef unsigned long long ull;

// ---------------- scratch (static device globals) ---------------------------
__device__ float g_xproj[(size_t)ROWS * G4];
__device__ __align__(16) float g_hs_buf[(size_t)(SEQ + 1) * HSLOT];  // [s][k][b]
__device__ float g_c[BATCH * HIDDEN];
__device__ float g_biasx[G4];
__device__ unsigned g_grp[16 * 64];        // group counters, 256B apart
__device__ unsigned g_root;
__device__ volatile unsigned g_epoch;

// bf16 hi/lo planes for HMMA GEMMs (row-major [m][k] / [n][k], k=512)
__device__ __align__(16) __nv_bfloat16 A_emb_hi[(size_t)ROWS * EMBED];
__device__ __align__(16) __nv_bfloat16 A_emb_lo[(size_t)ROWS * EMBED];
__device__ __align__(16) __nv_bfloat16 A_hs_hi[(size_t)ROWS * HIDDEN];
__device__ __align__(16) __nv_bfloat16 A_hs_lo[(size_t)ROWS * HIDDEN];
__device__ __align__(16) __nv_bfloat16 Bx_hi[(size_t)G4 * EMBED];
__device__ __align__(16) __nv_bfloat16 Bx_lo[(size_t)G4 * EMBED];
__device__ __align__(16) __nv_bfloat16 By_hi[(size_t)NPAD * HIDDEN];
__device__ __align__(16) __nv_bfloat16 By_lo[(size_t)NPAD * HIDDEN];

__device__ __forceinline__ float sigf(float x)  { return 1.0f / (1.0f + __expf(-x)); }
__device__ __forceinline__ float tanhx(float x) { return 2.0f / (1.0f + __expf(-2.0f * x)) - 1.0f; }

__device__ __forceinline__ ull pk2(float x) {
    ull r; asm("mov.b64 %0, {%1, %2};" : "=l"(r) : "f"(x), "f"(x)); return r;
}
__device__ __forceinline__ void unpk(ull v, float& lo, float& hi) {
    asm("mov.b64 {%0, %1}, %2;" : "=f"(lo), "=f"(hi) : "l"(v));
}
__device__ __forceinline__ void fma2(ull& d, ull a, ull b) {
    asm("fma.rn.f32x2 %0, %1, %2, %0;" : "+l"(d) : "l"(a), "l"(b));
}
__device__ __forceinline__ void cp_async16(void* dst, const void* src) {
    unsigned a = (unsigned)__cvta_generic_to_shared(dst);
    asm volatile("cp.async.cg.shared.global [%0], [%1], 16;" :: "r"(a), "l"(src));
}

#define SWZ(o) ((o) ^ (((o) >> 3) & 0x70))

__device__ __forceinline__ void ldm4(uint32_t* r, uint32_t a) {
    asm volatile("ldmatrix.sync.aligned.m8n8.x4.shared.b16 {%0,%1,%2,%3}, [%4];"
        : "=r"(r[0]), "=r"(r[1]), "=r"(r[2]), "=r"(r[3]) : "r"(a));
}
__device__ __forceinline__ void mma16816(float* d, const uint32_t* a, const uint32_t* b) {
    asm volatile("mma.sync.aligned.m16n8k16.row.col.f32.bf16.bf16.f32 "
        "{%0,%1,%2,%3}, {%4,%5,%6,%7}, {%8,%9}, {%0,%1,%2,%3};"
        : "+f"(d[0]), "+f"(d[1]), "+f"(d[2]), "+f"(d[3])
        : "r"(a[0]), "r"(a[1]), "r"(a[2]), "r"(a[3]), "r"(b[0]), "r"(b[1]));
}

// ---------------- init ------------------------------------------------------
__global__ void k_init() {
    int i = blockIdx.x * blockDim.x + threadIdx.x;
    if (i < HSLOT) g_hs_buf[i] = 0.0f;
    if (i < 16 * 64) g_grp[i] = 0u;
    if (i == 0) { g_root = 0u; g_epoch = 0u; }
}

// ---------------- convert kernels -------------------------------------------
__global__ void k_cvtA_emb(const int* __restrict__ idx, const float* __restrict__ emb) {
    size_t i = (size_t)blockIdx.x * 256 + threadIdx.x;   // ROWS*512
    int m = (int)(i >> 9), k = (int)(i & 511);
    float v = emb[(size_t)idx[m] * EMBED + k];
    __nv_bfloat16 h = __float2bfloat16(v);
    A_emb_hi[i] = h;
    A_emb_lo[i] = __float2bfloat16(v - __bfloat162float(h));
}

__global__ void k_cvtBx(const float* __restrict__ w0, const float* __restrict__ w1,
                        const float* __restrict__ w2, const float* __restrict__ w3,
                        const float* __restrict__ b0, const float* __restrict__ b1,
                        const float* __restrict__ b2, const float* __restrict__ b3) {
    int n = blockIdx.x * 256 + threadIdx.x;  // 0..2047
    int k = blockIdx.y;                      // 0..511
    int g = n >> 9, j = n & 511;
    const float* w = (g == 0) ? w0 : (g == 1) ? w1 : (g == 2) ? w2 : w3;
    float v = w[(size_t)k * HIDDEN + j];
    __nv_bfloat16 h = __float2bfloat16(v);
    Bx_hi[(size_t)n * 512 + k] = h;
    Bx_lo[(size_t)n * 512 + k] = __float2bfloat16(v - __bfloat162float(h));
    if (k == 0) {
        const float* bb = (g == 0) ? b0 : (g == 1) ? b1 : (g == 2) ? b2 : b3;
        g_biasx[n] = bb[j];
    }
}

// transpose-tiled: 64n x 64k per CTA, vectorized plane writes
__global__ __launch_bounds__(256) void k_cvtBy(const float* __restrict__ wy) {
    __shared__ float T[64][65];
    const int tid = threadIdx.x;
    const int n0 = blockIdx.x * 64, k0 = blockIdx.y * 64;
    #pragma unroll
    for (int it = 0; it < 16; it++) {
        int u = tid + 256 * it;          // 0..4095
        int kl = u >> 6, nl = u & 63;
        int n = n0 + nl;
        T[kl][nl] = (n < VOCAB) ? wy[(size_t)(k0 + kl) * VOCAB + n] : 0.0f;
    }
    __syncthreads();
    int nl = tid >> 2, kb = (tid & 3) * 16;
    __nv_bfloat16 hi16[16], lo16[16];
    #pragma unroll
    for (int q = 0; q < 16; q++) {
        float v = T[kb + q][nl];
        __nv_bfloat16 h = __float2bfloat16(v);
        hi16[q] = h;
        lo16[q] = __float2bfloat16(v - __bfloat162float(h));
    }
    size_t base = (size_t)(n0 + nl) * 512 + k0 + kb;
    *(uint4*)(By_hi + base)     = *(uint4*)&hi16[0];
    *(uint4*)(By_hi + base + 8) = *(uint4*)&hi16[8];
    *(uint4*)(By_lo + base)     = *(uint4*)&lo16[0];
    *(uint4*)(By_lo + base + 8) = *(uint4*)&lo16[8];
}

// ---------------- HMMA GEMM body (tile 128m x 256n, K=512) ------------------
#define GB_BUF 98304
#define GB_TOT 196608

__device__ __forceinline__ void gemm_hmma(
    const __nv_bfloat16* __restrict__ Ahi, const __nv_bfloat16* __restrict__ Alo,
    const __nv_bfloat16* __restrict__ Bhi, const __nv_bfloat16* __restrict__ Blo,
    const float* __restrict__ bias, float* __restrict__ out, int Ntot,
    int m0, int n0)
{
    extern __shared__ char sm[];
    const int tid = threadIdx.x;
    const int lid = tid & 31, wid = tid >> 5;
    const int mw = wid >> 2, nw = wid & 3;
    uint32_t smu = (uint32_t)__cvta_generic_to_shared(sm);

    float acc[4][8][4];
    #pragma unroll
    for (int a = 0; a < 4; a++)
        #pragma unroll
        for (int b = 0; b < 8; b++)
            #pragma unroll
            for (int c = 0; c < 4; c++) acc[a][b][c] = 0.0f;

    auto stage = [&](int c, int buf) {
        char* bb = sm + (size_t)buf * GB_BUF;
        #pragma unroll
        for (int it = 0; it < 24; it++) {
            int u = tid + it * 256;
            const char* src; char* dst;
            if (u < 2048) {
                int plane = u >> 10, idx = u & 1023;
                int row = idx >> 3, kq = idx & 7;
                const __nv_bfloat16* Ap = plane ? Alo : Ahi;
                src = (const char*)(Ap + (((size_t)(m0 + row)) << 9) + c * 64 + kq * 8);
                dst = bb + plane * 16384 + SWZ(row * 128 + kq * 16);
            } else {
                int v = u - 2048;
                int plane = v >> 11, idx = v & 2047;
                int row = idx >> 3, kq = idx & 7;
                const __nv_bfloat16* Bp = plane ? Blo : Bhi;
                src = (const char*)(Bp + (((size_t)(n0 + row)) << 9) + c * 64 + kq * 8);
                dst = bb + 32768 + plane * 32768 + SWZ(row * 128 + kq * 16);
            }
            cp_async16(dst, src);
        }
        asm volatile("cp.async.commit_group;" ::: "memory");
    };

    stage(0, 0);
    for (int ch = 0; ch < 8; ch++) {
        if (ch + 1 < 8) {
            stage(ch + 1, (ch + 1) & 1);
            asm volatile("cp.async.wait_group 1;" ::: "memory");
        } else {
            asm volatile("cp.async.wait_group 0;" ::: "memory");
        }
        __syncthreads();

        uint32_t sb = smu + (uint32_t)(ch & 1) * GB_BUF;
        #pragma unroll
        for (int k16 = 0; k16 < 4; k16++) {
            int kb = k16 * 16;
            uint32_t ah[4][4], al[4][4];
            #pragma unroll
            for (int mt = 0; mt < 4; mt++) {
                uint32_t off = (uint32_t)((mw * 64 + mt * 16 + (lid & 15)) * 128
                              + kb * 2 + ((lid >> 4) & 1) * 16);
                ldm4(ah[mt], sb + SWZ(off));
                ldm4(al[mt], sb + 16384 + SWZ(off));
            }
            #pragma unroll
            for (int ntp = 0; ntp < 4; ntp++) {
                uint32_t offb = (uint32_t)((nw * 64 + ntp * 16 + ((lid >> 4) & 1) * 8
                               + (lid & 7)) * 128 + kb * 2 + ((lid >> 3) & 1) * 16);
                uint32_t bh[4], bl[4];
                ldm4(bh, sb + 32768 + SWZ(offb));
                ldm4(bl, sb + 65536 + SWZ(offb));
                #pragma unroll
                for (int mt = 0; mt < 4; mt++) {
                    mma16816(acc[mt][ntp * 2],     ah[mt], bh + 0);
                    mma16816(acc[mt][ntp * 2],     ah[mt], bl + 0);
                    mma16816(acc[mt][ntp * 2],     al[mt], bh + 0);
                    mma16816(acc[mt][ntp * 2 + 1], ah[mt], bh + 2);
                    mma16816(acc[mt][ntp * 2 + 1], ah[mt], bl + 2);
                    mma16816(acc[mt][ntp * 2 + 1], al[mt], bh + 2);
                }
            }
        }
        __syncthreads();
    }

    const int rq = lid >> 2, cp2 = (lid & 3) * 2;
    #pragma unroll
    for (int mt = 0; mt < 4; mt++) {
        int mrow = m0 + mw * 64 + mt * 16 + rq;
        float* o0 = out + (size_t)mrow * Ntot;
        float* o1 = out + (size_t)(mrow + 8) * Ntot;
        #pragma unroll
        for (int nt = 0; nt < 8; nt++) {
            int n = n0 + nw * 64 + nt * 8 + cp2;
            if (n < Ntot) {
                float b0v = bias[n], b1v = bias[n + 1];
                *(float2*)(o0 + n) = make_float2(acc[mt][nt][0] + b0v, acc[mt][nt][1] + b1v);
                *(float2*)(o1 + n) = make_float2(acc[mt][nt][2] + b0v, acc[mt][nt][3] + b1v);
            }
        }
    }
}

__global__ __launch_bounds__(256, 1) void k_gemm_x() {
    gemm_hmma(A_emb_hi, A_emb_lo, Bx_hi, Bx_lo, g_biasx, g_xproj, G4,
              blockIdx.y * 128, blockIdx.x * 256);
}

// ---------------- LSTM recurrence body (R13, 512 threads) -------------------
#define LSM_W   0
#define LSM_H   32768
#define LSM_P   163840
#define LSM_X   204800
#define LSM_TOT 212992
#define PJ      5

__device__ __forceinline__ void lstm_body(
    const float* __restrict__ wh0, const float* __restrict__ wh1,
    const float* __restrict__ wh2, const float* __restrict__ wh3)
{
    extern __shared__ char sm[];
    float* Wf   = (float*)(sm + LSM_W);
    float* Hs   = (float*)(sm + LSM_H);
    float* Psum = (float*)(sm + LSM_P);

    const int tid = threadIdx.x;
    const int lid = tid & 31;
    const int wid = tid >> 5;
    const int ci  = blockIdx.x;
    const int e0  = ci * 4;

    for (int i = tid; i < 4 * 512; i += NTHR_L) {
        int k = i >> 2, g = i & 3;
        const float* w = (g == 0) ? wh0 : (g == 1) ? wh1 : (g == 2) ? wh2 : wh3;
        *(float4*)(Wf + (size_t)k * 16 + g * 4) =
            *(const float4*)(w + (size_t)k * HIDDEN + e0);
    }

    const int kg   = wid & 7;
    const int bh   = wid >> 3;
    const int gate = (tid >> 3) & 3;
    const int b0   = bh * 32 + (tid & 7) * 4;
    const int eb = tid >> 2;
    const int ej = tid & 3;
    float c_reg = 0.0f;

    if (tid < 256) {
        int g = tid >> 6, bb = tid & 63;
        cp_async16(sm + LSM_X + ((g * 64 + bb) * 4) * 4,
                   g_xproj + ((size_t)(0 * BATCH + bb)) * G4 + g * HIDDEN + e0);
    }
    asm volatile("cp.async.commit_group;" ::: "memory");
    asm volatile("cp.async.wait_group 0;" ::: "memory");
    __syncthreads();

    for (int s = 0; s < SEQ; s++) {
        const float* hsrc = g_hs_buf + (size_t)s * HSLOT;

        #pragma unroll
        for (int hf = 0; hf < 2; hf++) {
            #pragma unroll
            for (int j = 0; j < 8; j++) {
                int u = lid + 32 * j;
                int q = u >> 3, seg = u & 7;
                int k = kg * 64 + hf * 32 + q;
                cp_async16(Hs + (size_t)k * 64 + bh * 32 + seg * 4,
                           hsrc + (size_t)k * 64 + bh * 32 + seg * 4);
            }
            if (hf == 1 && tid < 256) {
                int sn = (s + 1 < SEQ) ? s + 1 : s;
                int g = tid >> 6, bb = tid & 63;
                cp_async16(sm + LSM_X + 4096 * ((s + 1) & 1) + ((g * 64 + bb) * 4) * 4,
                           g_xproj + ((size_t)(sn * BATCH + bb)) * G4 + g * HIDDEN + e0);
            }
            asm volatile("cp.async.commit_group;" ::: "memory");
        }

        ull acc[8];
        #pragma unroll
        for (int i = 0; i < 8; i++) acc[i] = 0ull;

        const float* wbp = Wf + (size_t)(kg * 64) * 16 + gate * 4;
        const float* hbase = Hs + (size_t)(kg * 64) * 64 + b0;

        asm volatile("cp.async.wait_group 1;" ::: "memory");
        __syncwarp();
        #pragma unroll 8
        for (int kk = 0; kk < 32; kk++) {
            float4 w4 = *(const float4*)(wbp + kk * 16);
            ulonglong2 hh = *(const ulonglong2*)(hbase + kk * 64);
            ull wx = pk2(w4.x), wyv = pk2(w4.y), wz = pk2(w4.z), ww = pk2(w4.w);
            fma2(acc[0], hh.x, wx);  fma2(acc[1], hh.y, wx);
            fma2(acc[2], hh.x, wyv); fma2(acc[3], hh.y, wyv);
            fma2(acc[4], hh.x, wz);  fma2(acc[5], hh.y, wz);
            fma2(acc[6], hh.x, ww);  fma2(acc[7], hh.y, ww);
        }
        asm volatile("cp.async.wait_group 0;" ::: "memory");
        __syncwarp();
        #pragma unroll 8
        for (int kk = 32; kk < 64; kk++) {
            float4 w4 = *(const float4*)(wbp + kk * 16);
            ulonglong2 hh = *(const ulonglong2*)(hbase + kk * 64);
            ull wx = pk2(w4.x), wyv = pk2(w4.y), wz = pk2(w4.z), ww = pk2(w4.w);
            fma2(acc[0], hh.x, wx);  fma2(acc[1], hh.y, wx);
            fma2(acc[2], hh.x, wyv); fma2(acc[3], hh.y, wyv);
            fma2(acc[4], hh.x, wz);  fma2(acc[5], hh.y, wz);
            fma2(acc[6], hh.x, ww);  fma2(acc[7], hh.y, ww);
        }

        #pragma unroll
        for (int e = 0; e < 4; e++)
            #pragma unroll
            for (int p = 0; p < 2; p++) {
                float lo, hi; unpk(acc[e * 2 + p], lo, hi);
                Psum[((kg * 4 + gate) * 64 + b0 + 2 * p)     * PJ + e] = lo;
                Psum[((kg * 4 + gate) * 64 + b0 + 2 * p + 1) * PJ + e] = hi;
            }
        __syncthreads();

        if (tid < 256) {
            const float* Xsf = (const float*)(sm + LSM_X + 4096 * (s & 1));
            float gi = Xsf[(0 * 64 + eb) * 4 + ej];
            float gf = Xsf[(1 * 64 + eb) * 4 + ej];
            float gc = Xsf[(2 * 64 + eb) * 4 + ej];
            float go = Xsf[(3 * 64 + eb) * 4 + ej];
            #pragma unroll
            for (int q = 0; q < 8; q++) {
                gi += Psum[((q * 4 + 0) * 64 + eb) * PJ + ej];
                gf += Psum[((q * 4 + 1) * 64 + eb) * PJ + ej];
                gc += Psum[((q * 4 + 2) * 64 + eb) * PJ + ej];
                go += Psum[((q * 4 + 3) * 64 + eb) * PJ + ej];
            }
            c_reg = sigf(gf) * c_reg + sigf(gi) * tanhx(gc);
            float hval = sigf(go) * tanhx(c_reg);
            g_hs_buf[(size_t)(s + 1) * HSLOT + (e0 + ej) * 64 + eb] = hval;
            __nv_bfloat16 hb16 = __float2bfloat16(hval);
            size_t ai = ((size_t)(s * BATCH + eb)) * HIDDEN + e0 + ej;
            A_hs_hi[ai] = hb16;
            A_hs_lo[ai] = __float2bfloat16(hval - __bfloat162float(hb16));
        }

        // ---- hierarchical barrier; ALWAYS arrive (gemm CTAs consume epoch) -
        __syncthreads();
        if (tid == 0) {
            __threadfence();
            unsigned g = atomicAdd(&g_grp[(ci >> 3) * 64], 1u);
            if (g == (unsigned)(s * 8 + 7)) {
                unsigned r = atomicAdd(&g_root, 1u);
                if (r == (unsigned)(s * 16 + 15)) {
                    __threadfence();
                    g_epoch = (unsigned)(s + 1);
                }
            }
            if (s + 1 < SEQ) {
                while (g_epoch < (unsigned)(s + 1)) __nanosleep(32);
                __threadfence();
            }
        }
        if (s + 1 < SEQ) __syncthreads();
    }

    if (tid < 256) g_c[eb * HIDDEN + e0 + ej] = c_reg;
}

// ---------------- fused persistent LSTM + overlapped output GEMM ------------
__global__ __launch_bounds__(512, 1) void k_fused(
    const float* __restrict__ wh0, const float* __restrict__ wh1,
    const float* __restrict__ wh2, const float* __restrict__ wh3,
    const float* __restrict__ by, float* __restrict__ out)
{
    if (blockIdx.x < NCTA) {
        lstm_body(wh0, wh1, wh2, wh3);
        return;
    }
    // output-GEMM tile, gated on recurrence progress
    if (threadIdx.x >= 256) return;
    int t  = blockIdx.x - NCTA;
    int my = t / 40, nx = t % 40;     // ascending my => early tiles first
    unsigned need = (unsigned)(2 * my + 2);
    if (threadIdx.x == 0) {
        while (g_epoch < need) __nanosleep(128);
    }
    __syncthreads();
    __threadfence();                  // acquire: order A_hs reads after epoch
    gemm_hmma(A_hs_hi, A_hs_lo, By_hi, By_lo, by, out, VOCAB,
              my * 128, nx * 256);
}

// ---------------- tail: ht, ct ---------------------------------------------
__global__ void k_tail(float* out) {
    int i = blockIdx.x * blockDim.x + threadIdx.x;
    size_t base = (size_t)ROWS * VOCAB;
    if (i < BATCH * HIDDEN) {
        int b = i >> 9, e = i & 511;
        out[base + i] = g_hs_buf[(size_t)SEQ * HSLOT + e * 64 + b];
    } else if (i < 2 * BATCH * HIDDEN) {
        out[base + i] = g_c[i - BATCH * HIDDEN];
    }
}

// ---------------- launch ----------------------------------------------------
extern "C" void kernel_launch(void* const* d_in, const int* in_sizes, int n_in,
                              void* d_out, int out_size) {
    const int*   input_ = (const int*)  d_in[0];
    const float* emb    = (const float*)d_in[1];
    const float* wxi    = (const float*)d_in[2];
    const float* whi    = (const float*)d_in[3];
    const float* bi     = (const float*)d_in[4];
    const float* wxf    = (const float*)d_in[5];
    const float* whf    = (const float*)d_in[6];
    const float* bf     = (const float*)d_in[7];
    const float* wxc    = (const float*)d_in[8];
    const float* whc    = (const float*)d_in[9];
    const float* bc     = (const float*)d_in[10];
    const float* wxo    = (const float*)d_in[11];
    const float* who    = (const float*)d_in[12];
    const float* bo     = (const float*)d_in[13];
    const float* wy     = (const float*)d_in[14];
    const float* by     = (const float*)d_in[15];
    float* out = (float*)d_out;

    cudaFuncSetAttribute(k_fused,  cudaFuncAttributeMaxDynamicSharedMemorySize, LSM_TOT);
    cudaFuncSetAttribute(k_gemm_x, cudaFuncAttributeMaxDynamicSharedMemorySize, GB_TOT);

    k_init<<<NCTA, NTHR>>>();

    k_cvtA_emb<<<(ROWS * EMBED) / 256, 256>>>(input_, emb);
    k_cvtBx<<<dim3(8, 512), 256>>>(wxi, wxf, wxc, wxo, bi, bf, bc, bo);
    k_cvtBy<<<dim3(160, 8), 256>>>(wy);

    k_gemm_x<<<dim3(8, 128), 256, GB_TOT>>>();

    k_fused<<<NCTA + 128 * 40, NTHR_L, LSM_TOT>>>(whi, whf, whc, who, by, out);

    if ((long long)out_size >= (long long)ROWS * VOCAB + 2LL * BATCH * HIDDEN)
        k_tail<<<(2 * BATCH * HIDDEN + 255) / 256, 256>>>(out);
}

// round 17
// speedup vs baseline: 1.7329x; 1.7329x over previous
#include <cuda_runtime.h>
#include <cuda_bf16.h>
#include <math.h>
#include <stdint.h>

#define SEQ    256
#define BATCH  64
#define EMBED  512
#define HIDDEN 512
#define VOCAB  10000
#define NPAD   10240
#define ROWS   (SEQ*BATCH)      /* 16384 */
#define G4     (4*HIDDEN)       /* 2048  */
#define NCTA   128
#define NTHR   256
#define NTHR_L 512
#define HSLOT  (HIDDEN*BATCH)   /* 32768 floats per h slot */

typedef unsigned long long ull;

// ---------------- scratch (static device globals) ---------------------------
__device__ float g_xproj[(size_t)ROWS * G4];
__device__ __align__(16) float g_hs_buf[(size_t)(SEQ + 1) * HSLOT];  // [s][k][b]
__device__ float g_c[BATCH * HIDDEN];
__device__ float g_biasx[G4];
__device__ unsigned g_grp[16 * 64];        // group counters, 256B apart
__device__ unsigned g_root;
__device__ volatile unsigned g_epoch;

// bf16 hi/lo planes for HMMA GEMMs (row-major [m][k] / [n][k], k=512)
__device__ __align__(16) __nv_bfloat16 A_emb_hi[(size_t)ROWS * EMBED];
__device__ __align__(16) __nv_bfloat16 A_emb_lo[(size_t)ROWS * EMBED];
__device__ __align__(16) __nv_bfloat16 A_hs_hi[(size_t)ROWS * HIDDEN];
__device__ __align__(16) __nv_bfloat16 A_hs_lo[(size_t)ROWS * HIDDEN];
__device__ __align__(16) __nv_bfloat16 Bx_hi[(size_t)G4 * EMBED];
__device__ __align__(16) __nv_bfloat16 Bx_lo[(size_t)G4 * EMBED];
__device__ __align__(16) __nv_bfloat16 By_hi[(size_t)NPAD * HIDDEN];
__device__ __align__(16) __nv_bfloat16 By_lo[(size_t)NPAD * HIDDEN];

__device__ __forceinline__ float sigf(float x)  { return 1.0f / (1.0f + __expf(-x)); }
__device__ __forceinline__ float tanhx(float x) { return 2.0f / (1.0f + __expf(-2.0f * x)) - 1.0f; }

__device__ __forceinline__ ull pk2(float x) {
    ull r; asm("mov.b64 %0, {%1, %2};" : "=l"(r) : "f"(x), "f"(x)); return r;
}
__device__ __forceinline__ void unpk(ull v, float& lo, float& hi) {
    asm("mov.b64 {%0, %1}, %2;" : "=f"(lo), "=f"(hi) : "l"(v));
}
__device__ __forceinline__ void fma2(ull& d, ull a, ull b) {
    asm("fma.rn.f32x2 %0, %1, %2, %0;" : "+l"(d) : "l"(a), "l"(b));
}
__device__ __forceinline__ void cp_async16(void* dst, const void* src) {
    unsigned a = (unsigned)__cvta_generic_to_shared(dst);
    asm volatile("cp.async.cg.shared.global [%0], [%1], 16;" :: "r"(a), "l"(src));
}

#define SWZ(o) ((o) ^ (((o) >> 3) & 0x70))

__device__ __forceinline__ void ldm4(uint32_t* r, uint32_t a) {
    asm volatile("ldmatrix.sync.aligned.m8n8.x4.shared.b16 {%0,%1,%2,%3}, [%4];"
        : "=r"(r[0]), "=r"(r[1]), "=r"(r[2]), "=r"(r[3]) : "r"(a));
}
__device__ __forceinline__ void mma16816(float* d, const uint32_t* a, const uint32_t* b) {
    asm volatile("mma.sync.aligned.m16n8k16.row.col.f32.bf16.bf16.f32 "
        "{%0,%1,%2,%3}, {%4,%5,%6,%7}, {%8,%9}, {%0,%1,%2,%3};"
        : "+f"(d[0]), "+f"(d[1]), "+f"(d[2]), "+f"(d[3])
        : "r"(a[0]), "r"(a[1]), "r"(a[2]), "r"(a[3]), "r"(b[0]), "r"(b[1]));
}

// ---------------- init (slim) ------------------------------------------------
__global__ void k_init() {
    int i = blockIdx.x * blockDim.x + threadIdx.x;   // 33 blocks x 256
    if (i < HSLOT / 4) {
        *(float4*)(g_hs_buf + (size_t)i * 4) = make_float4(0.f, 0.f, 0.f, 0.f);
    }
    if (i >= HSLOT / 4) {
        int j = i - HSLOT / 4;
        if (j < 16 * 64) g_grp[j] = 0u;
        if (j == 16 * 64) { g_root = 0u; g_epoch = 0u; }
    }
}

// ---------------- convert kernels -------------------------------------------
// vectorized: 8 elems/thread; one float4x2 gather load, two uint4 plane stores
__global__ void k_cvtA_emb(const int* __restrict__ idx, const float* __restrict__ emb) {
    size_t t = (size_t)blockIdx.x * 256 + threadIdx.x;   // ROWS*512/8 threads
    int m = (int)(t >> 6), k8 = (int)(t & 63) * 8;
    const float* src = emb + (size_t)idx[m] * EMBED + k8;
    float4 v0 = *(const float4*)(src);
    float4 v1 = *(const float4*)(src + 4);
    __nv_bfloat16 hi[8], lo[8];
    float vv[8] = {v0.x, v0.y, v0.z, v0.w, v1.x, v1.y, v1.z, v1.w};
    #pragma unroll
    for (int q = 0; q < 8; q++) {
        __nv_bfloat16 h = __float2bfloat16(vv[q]);
        hi[q] = h;
        lo[q] = __float2bfloat16(vv[q] - __bfloat162float(h));
    }
    size_t base = (size_t)m * EMBED + k8;
    *(uint4*)(A_emb_hi + base) = *(uint4*)&hi[0];
    *(uint4*)(A_emb_lo + base) = *(uint4*)&lo[0];
}

// transpose-tiled like cvtBy: 64n x 64k per CTA
__global__ __launch_bounds__(256) void k_cvtBx(
    const float* __restrict__ w0, const float* __restrict__ w1,
    const float* __restrict__ w2, const float* __restrict__ w3,
    const float* __restrict__ b0, const float* __restrict__ b1,
    const float* __restrict__ b2, const float* __restrict__ b3)
{
    __shared__ float T[64][65];
    const int tid = threadIdx.x;
    const int n0 = blockIdx.x * 64;     // 32 blocks: n in [0,2048)
    const int k0 = blockIdx.y * 64;     // 8 blocks
    const int g = n0 >> 9;              // 64-wide tile never crosses gate bound
    const float* w = (g == 0) ? w0 : (g == 1) ? w1 : (g == 2) ? w2 : w3;
    const int j0 = n0 & 511;
    #pragma unroll
    for (int it = 0; it < 16; it++) {
        int u = tid + 256 * it;
        int kl = u >> 6, nl = u & 63;
        T[kl][nl] = w[(size_t)(k0 + kl) * HIDDEN + j0 + nl];
    }
    __syncthreads();
    int nl = tid >> 2, kb = (tid & 3) * 16;
    __nv_bfloat16 hi16[16], lo16[16];
    #pragma unroll
    for (int q = 0; q < 16; q++) {
        float v = T[kb + q][nl];
        __nv_bfloat16 h = __float2bfloat16(v);
        hi16[q] = h;
        lo16[q] = __float2bfloat16(v - __bfloat162float(h));
    }
    size_t base = (size_t)(n0 + nl) * 512 + k0 + kb;
    *(uint4*)(Bx_hi + base)     = *(uint4*)&hi16[0];
    *(uint4*)(Bx_hi + base + 8) = *(uint4*)&hi16[8];
    *(uint4*)(Bx_lo + base)     = *(uint4*)&lo16[0];
    *(uint4*)(Bx_lo + base + 8) = *(uint4*)&lo16[8];
    if (blockIdx.y == 0 && tid < 64) {
        const float* bb = (g == 0) ? b0 : (g == 1) ? b1 : (g == 2) ? b2 : b3;
        g_biasx[n0 + tid] = bb[j0 + tid];
    }
}

// transpose-tiled: 64n x 64k per CTA, vectorized plane writes
__global__ __launch_bounds__(256) void k_cvtBy(const float* __restrict__ wy) {
    __shared__ float T[64][65];
    const int tid = threadIdx.x;
    const int n0 = blockIdx.x * 64, k0 = blockIdx.y * 64;
    #pragma unroll
    for (int it = 0; it < 16; it++) {
        int u = tid + 256 * it;          // 0..4095
        int kl = u >> 6, nl = u & 63;
        int n = n0 + nl;
        T[kl][nl] = (n < VOCAB) ? wy[(size_t)(k0 + kl) * VOCAB + n] : 0.0f;
    }
    __syncthreads();
    int nl = tid >> 2, kb = (tid & 3) * 16;
    __nv_bfloat16 hi16[16], lo16[16];
    #pragma unroll
    for (int q = 0; q < 16; q++) {
        float v = T[kb + q][nl];
        __nv_bfloat16 h = __float2bfloat16(v);
        hi16[q] = h;
        lo16[q] = __float2bfloat16(v - __bfloat162float(h));
    }
    size_t base = (size_t)(n0 + nl) * 512 + k0 + kb;
    *(uint4*)(By_hi + base)     = *(uint4*)&hi16[0];
    *(uint4*)(By_hi + base + 8) = *(uint4*)&hi16[8];
    *(uint4*)(By_lo + base)     = *(uint4*)&lo16[0];
    *(uint4*)(By_lo + base + 8) = *(uint4*)&lo16[8];
}

// ---------------- HMMA GEMM (tile 128m x 256n, K=512) -----------------------
#define GB_BUF 98304
#define GB_TOT 196608

__device__ __forceinline__ void gemm_hmma(
    const __nv_bfloat16* __restrict__ Ahi, const __nv_bfloat16* __restrict__ Alo,
    const __nv_bfloat16* __restrict__ Bhi, const __nv_bfloat16* __restrict__ Blo,
    const float* __restrict__ bias, float* __restrict__ out, int Ntot)
{
    extern __shared__ char sm[];
    const int tid = threadIdx.x;
    const int lid = tid & 31, wid = tid >> 5;
    const int mw = wid >> 2, nw = wid & 3;
    const int n0 = blockIdx.x * 256;
    const int m0 = blockIdx.y * 128;
    uint32_t smu = (uint32_t)__cvta_generic_to_shared(sm);

    float acc[4][8][4];
    #pragma unroll
    for (int a = 0; a < 4; a++)
        #pragma unroll
        for (int b = 0; b < 8; b++)
            #pragma unroll
            for (int c = 0; c < 4; c++) acc[a][b][c] = 0.0f;

    auto stage = [&](int c, int buf) {
        char* bb = sm + (size_t)buf * GB_BUF;
        #pragma unroll
        for (int it = 0; it < 24; it++) {
            int u = tid + it * 256;
            const char* src; char* dst;
            if (u < 2048) {
                int plane = u >> 10, idx = u & 1023;
                int row = idx >> 3, kq = idx & 7;
                const __nv_bfloat16* Ap = plane ? Alo : Ahi;
                src = (const char*)(Ap + (((size_t)(m0 + row)) << 9) + c * 64 + kq * 8);
                dst = bb + plane * 16384 + SWZ(row * 128 + kq * 16);
            } else {
                int v = u - 2048;
                int plane = v >> 11, idx = v & 2047;
                int row = idx >> 3, kq = idx & 7;
                const __nv_bfloat16* Bp = plane ? Blo : Bhi;
                src = (const char*)(Bp + (((size_t)(n0 + row)) << 9) + c * 64 + kq * 8);
                dst = bb + 32768 + plane * 32768 + SWZ(row * 128 + kq * 16);
            }
            cp_async16(dst, src);
        }
        asm volatile("cp.async.commit_group;" ::: "memory");
    };

    stage(0, 0);
    for (int ch = 0; ch < 8; ch++) {
        if (ch + 1 < 8) {
            stage(ch + 1, (ch + 1) & 1);
            asm volatile("cp.async.wait_group 1;" ::: "memory");
        } else {
            asm volatile("cp.async.wait_group 0;" ::: "memory");
        }
        __syncthreads();

        uint32_t sb = smu + (uint32_t)(ch & 1) * GB_BUF;
        #pragma unroll
        for (int k16 = 0; k16 < 4; k16++) {
            int kb = k16 * 16;
            uint32_t ah[4][4], al[4][4];
            #pragma unroll
            for (int mt = 0; mt < 4; mt++) {
                uint32_t off = (uint32_t)((mw * 64 + mt * 16 + (lid & 15)) * 128
                              + kb * 2 + ((lid >> 4) & 1) * 16);
                ldm4(ah[mt], sb + SWZ(off));
                ldm4(al[mt], sb + 16384 + SWZ(off));
            }
            #pragma unroll
            for (int ntp = 0; ntp < 4; ntp++) {
                uint32_t offb = (uint32_t)((nw * 64 + ntp * 16 + ((lid >> 4) & 1) * 8
                               + (lid & 7)) * 128 + kb * 2 + ((lid >> 3) & 1) * 16);
                uint32_t bh[4], bl[4];
                ldm4(bh, sb + 32768 + SWZ(offb));
                ldm4(bl, sb + 65536 + SWZ(offb));
                #pragma unroll
                for (int mt = 0; mt < 4; mt++) {
                    mma16816(acc[mt][ntp * 2],     ah[mt], bh + 0);
                    mma16816(acc[mt][ntp * 2],     ah[mt], bl + 0);
                    mma16816(acc[mt][ntp * 2],     al[mt], bh + 0);
                    mma16816(acc[mt][ntp * 2 + 1], ah[mt], bh + 2);
                    mma16816(acc[mt][ntp * 2 + 1], ah[mt], bl + 2);
                    mma16816(acc[mt][ntp * 2 + 1], al[mt], bh + 2);
                }
            }
        }
        __syncthreads();
    }

    const int rq = lid >> 2, cp2 = (lid & 3) * 2;
    #pragma unroll
    for (int mt = 0; mt < 4; mt++) {
        int mrow = m0 + mw * 64 + mt * 16 + rq;
        float* o0 = out + (size_t)mrow * Ntot;
        float* o1 = out + (size_t)(mrow + 8) * Ntot;
        #pragma unroll
        for (int nt = 0; nt < 8; nt++) {
            int n = n0 + nw * 64 + nt * 8 + cp2;
            if (n < Ntot) {
                float b0v = bias[n], b1v = bias[n + 1];
                *(float2*)(o0 + n) = make_float2(acc[mt][nt][0] + b0v, acc[mt][nt][1] + b1v);
                *(float2*)(o1 + n) = make_float2(acc[mt][nt][2] + b0v, acc[mt][nt][3] + b1v);
            }
        }
    }
}

__global__ __launch_bounds__(256, 1) void k_gemm_x() {
    gemm_hmma(A_emb_hi, A_emb_lo, Bx_hi, Bx_lo, g_biasx, g_xproj, G4);
}
__global__ __launch_bounds__(256, 1) void k_gemm_o(const float* __restrict__ by,
                                                   float* __restrict__ out) {
    gemm_hmma(A_hs_hi, A_hs_lo, By_hi, By_lo, by, out, VOCAB);
}

// ---------------- persistent LSTM recurrence (R13) ---------------------------
// 512 threads (4 warps/SMSP). Warp = (kg 0..7, bh 0..1): K-slice x batch-half.
#define LSM_W   0
#define LSM_H   32768
#define LSM_P   163840
#define LSM_X   204800
#define LSM_TOT 212992
#define PJ      5

__global__ __launch_bounds__(512, 1) void k_lstm(
    const float* __restrict__ wh0, const float* __restrict__ wh1,
    const float* __restrict__ wh2, const float* __restrict__ wh3)
{
    extern __shared__ char sm[];
    float* Wf   = (float*)(sm + LSM_W);
    float* Hs   = (float*)(sm + LSM_H);
    float* Psum = (float*)(sm + LSM_P);

    const int tid = threadIdx.x;
    const int lid = tid & 31;
    const int wid = tid >> 5;
    const int ci  = blockIdx.x;
    const int e0  = ci * 4;

    for (int i = tid; i < 4 * 512; i += NTHR_L) {
        int k = i >> 2, g = i & 3;
        const float* w = (g == 0) ? wh0 : (g == 1) ? wh1 : (g == 2) ? wh2 : wh3;
        *(float4*)(Wf + (size_t)k * 16 + g * 4) =
            *(const float4*)(w + (size_t)k * HIDDEN + e0);
    }

    const int kg   = wid & 7;          // K slice (64 kk)
    const int bh   = wid >> 3;         // batch half (32 b)
    const int gate = (tid >> 3) & 3;
    const int b0   = bh * 32 + (tid & 7) * 4;
    const int eb = tid >> 2;           // epilogue (tid<256): batch
    const int ej = tid & 3;            // epilogue: col
    float c_reg = 0.0f;

    if (tid < 256) {
        int g = tid >> 6, bb = tid & 63;
        cp_async16(sm + LSM_X + ((g * 64 + bb) * 4) * 4,
                   g_xproj + ((size_t)(0 * BATCH + bb)) * G4 + g * HIDDEN + e0);
    }
    asm volatile("cp.async.commit_group;" ::: "memory");
    asm volatile("cp.async.wait_group 0;" ::: "memory");
    __syncthreads();

    for (int s = 0; s < SEQ; s++) {
        const float* hsrc = g_hs_buf + (size_t)s * HSLOT;   // [k][64b]

        #pragma unroll
        for (int hf = 0; hf < 2; hf++) {
            #pragma unroll
            for (int j = 0; j < 8; j++) {
                int u = lid + 32 * j;              // 0..255 (16B units)
                int q = u >> 3, seg = u & 7;
                int k = kg * 64 + hf * 32 + q;
                cp_async16(Hs + (size_t)k * 64 + bh * 32 + seg * 4,
                           hsrc + (size_t)k * 64 + bh * 32 + seg * 4);
            }
            if (hf == 1 && tid < 256) {
                int sn = (s + 1 < SEQ) ? s + 1 : s;
                int g = tid >> 6, bb = tid & 63;
                cp_async16(sm + LSM_X + 4096 * ((s + 1) & 1) + ((g * 64 + bb) * 4) * 4,
                           g_xproj + ((size_t)(sn * BATCH + bb)) * G4 + g * HIDDEN + e0);
            }
            asm volatile("cp.async.commit_group;" ::: "memory");
        }

        ull acc[8];
        #pragma unroll
        for (int i = 0; i < 8; i++) acc[i] = 0ull;

        const float* wbp = Wf + (size_t)(kg * 64) * 16 + gate * 4;
        const float* hbase = Hs + (size_t)(kg * 64) * 64 + b0;

        asm volatile("cp.async.wait_group 1;" ::: "memory");
        __syncwarp();
        #pragma unroll 8
        for (int kk = 0; kk < 32; kk++) {
            float4 w4 = *(const float4*)(wbp + kk * 16);
            ulonglong2 hh = *(const ulonglong2*)(hbase + kk * 64);
            ull wx = pk2(w4.x), wyv = pk2(w4.y), wz = pk2(w4.z), ww = pk2(w4.w);
            fma2(acc[0], hh.x, wx);  fma2(acc[1], hh.y, wx);
            fma2(acc[2], hh.x, wyv); fma2(acc[3], hh.y, wyv);
            fma2(acc[4], hh.x, wz);  fma2(acc[5], hh.y, wz);
            fma2(acc[6], hh.x, ww);  fma2(acc[7], hh.y, ww);
        }
        asm volatile("cp.async.wait_group 0;" ::: "memory");
        __syncwarp();
        #pragma unroll 8
        for (int kk = 32; kk < 64; kk++) {
            float4 w4 = *(const float4*)(wbp + kk * 16);
            ulonglong2 hh = *(const ulonglong2*)(hbase + kk * 64);
            ull wx = pk2(w4.x), wyv = pk2(w4.y), wz = pk2(w4.z), ww = pk2(w4.w);
            fma2(acc[0], hh.x, wx);  fma2(acc[1], hh.y, wx);
            fma2(acc[2], hh.x, wyv); fma2(acc[3], hh.y, wyv);
            fma2(acc[4], hh.x, wz);  fma2(acc[5], hh.y, wz);
            fma2(acc[6], hh.x, ww);  fma2(acc[7], hh.y, ww);
        }

        #pragma unroll
        for (int e = 0; e < 4; e++)
            #pragma unroll
            for (int p = 0; p < 2; p++) {
                float lo, hi; unpk(acc[e * 2 + p], lo, hi);
                Psum[((kg * 4 + gate) * 64 + b0 + 2 * p)     * PJ + e] = lo;
                Psum[((kg * 4 + gate) * 64 + b0 + 2 * p + 1) * PJ + e] = hi;
            }
        __syncthreads();

        if (tid < 256) {
            const float* Xsf = (const float*)(sm + LSM_X + 4096 * (s & 1));
            float gi = Xsf[(0 * 64 + eb) * 4 + ej];
            float gf = Xsf[(1 * 64 + eb) * 4 + ej];
            float gc = Xsf[(2 * 64 + eb) * 4 + ej];
            float go = Xsf[(3 * 64 + eb) * 4 + ej];
            #pragma unroll
            for (int q = 0; q < 8; q++) {
                gi += Psum[((q * 4 + 0) * 64 + eb) * PJ + ej];
                gf += Psum[((q * 4 + 1) * 64 + eb) * PJ + ej];
                gc += Psum[((q * 4 + 2) * 64 + eb) * PJ + ej];
                go += Psum[((q * 4 + 3) * 64 + eb) * PJ + ej];
            }
            c_reg = sigf(gf) * c_reg + sigf(gi) * tanhx(gc);
            float hval = sigf(go) * tanhx(c_reg);
            g_hs_buf[(size_t)(s + 1) * HSLOT + (e0 + ej) * 64 + eb] = hval;
            __nv_bfloat16 hb16 = __float2bfloat16(hval);
            size_t ai = ((size_t)(s * BATCH + eb)) * HIDDEN + e0 + ej;
            A_hs_hi[ai] = hb16;
            A_hs_lo[ai] = __float2bfloat16(hval - __bfloat162float(hb16));
        }

        __syncthreads();
        if (s + 1 < SEQ) {
            if (tid == 0) {
                __threadfence();
                unsigned g = atomicAdd(&g_grp[(ci >> 3) * 64], 1u);
                if (g == (unsigned)(s * 8 + 7)) {
                    unsigned r = atomicAdd(&g_root, 1u);
                    if (r == (unsigned)(s * 16 + 15)) {
                        __threadfence();
                        g_epoch = (unsigned)(s + 1);
                    }
                }
                while (g_epoch < (unsigned)(s + 1)) __nanosleep(32);
                __threadfence();
            }
            __syncthreads();
        }
    }

    if (tid < 256) g_c[eb * HIDDEN + e0 + ej] = c_reg;
}

// ---------------- tail: ht, ct ---------------------------------------------
__global__ void k_tail(float* out) {
    int i = blockIdx.x * blockDim.x + threadIdx.x;
    size_t base = (size_t)ROWS * VOCAB;
    if (i < BATCH * HIDDEN) {
        int b = i >> 9, e = i & 511;
        out[base + i] = g_hs_buf[(size_t)SEQ * HSLOT + e * 64 + b];
    } else if (i < 2 * BATCH * HIDDEN) {
        out[base + i] = g_c[i - BATCH * HIDDEN];
    }
}

// ---------------- launch ----------------------------------------------------
extern "C" void kernel_launch(void* const* d_in, const int* in_sizes, int n_in,
                              void* d_out, int out_size) {
    const int*   input_ = (const int*)  d_in[0];
    const float* emb    = (const float*)d_in[1];
    const float* wxi    = (const float*)d_in[2];
    const float* whi    = (const float*)d_in[3];
    const float* bi     = (const float*)d_in[4];
    const float* wxf    = (const float*)d_in[5];
    const float* whf    = (const float*)d_in[6];
    const float* bf     = (const float*)d_in[7];
    const float* wxc    = (const float*)d_in[8];
    const float* whc    = (const float*)d_in[9];
    const float* bc     = (const float*)d_in[10];
    const float* wxo    = (const float*)d_in[11];
    const float* who    = (const float*)d_in[12];
    const float* bo     = (const float*)d_in[13];
    const float* wy     = (const float*)d_in[14];
    const float* by     = (const float*)d_in[15];
    float* out = (float*)d_out;

    cudaFuncSetAttribute(k_lstm,   cudaFuncAttributeMaxDynamicSharedMemorySize, LSM_TOT);
    cudaFuncSetAttribute(k_gemm_x, cudaFuncAttributeMaxDynamicSharedMemorySize, GB_TOT);
    cudaFuncSetAttribute(k_gemm_o, cudaFuncAttributeMaxDynamicSharedMemorySize, GB_TOT);

    k_init<<<34, 256>>>();

    k_cvtA_emb<<<(ROWS * EMBED) / (256 * 8), 256>>>(input_, emb);
    k_cvtBx<<<dim3(32, 8), 256>>>(wxi, wxf, wxc, wxo, bi, bf, bc, bo);
    k_cvtBy<<<dim3(160, 8), 256>>>(wy);

    k_gemm_x<<<dim3(8, 128), 256, GB_TOT>>>();

    k_lstm<<<NCTA, NTHR_L, LSM_TOT>>>(whi, whf, whc, who);

    k_gemm_o<<<dim3(40, 128), 256, GB_TOT>>>(by, out);

    if ((long long)out_size >= (long long)ROWS * VOCAB + 2LL * BATCH * HIDDEN)
        k_tail<<<(2 * BATCH * HIDDEN + 255) / 256, 256>>>(out);
}